// round 11
// baseline (speedup 1.0000x reference)
#include <cuda_runtime.h>

#define H1   1000
#define NCH1 1344     // layer-1 row chunks
#define RPC1 25       // rows per chunk (1344*25 = 33600)

#define NS   307      // needed layer-2 columns (x2[15k+1])
#define KC2  40       // layer-2 k chunks
#define RPC2 25       // rows per chunk (40*25 = 1000)

// ---------------- scratch (__device__ globals; no allocations) ----------------
__device__ float g_part1[NCH1 * H1];         // layer-1 partial sums [chunk][j]
__device__ float g_part2[KC2 * 320];         // layer-2 partials for the 307 scalars

// ---------------- L2 prefetch: warm Wb + Wd2 lines while l1 streams Wd1 ------
// 128B-line counts: W1b 80016, W2b 804, W3b 1004, W4b 4819, Wd2 143907
__global__ void __launch_bounds__(256) k_prefetch(
    const float* __restrict__ W1b, const float* __restrict__ W2b,
    const float* __restrict__ W3b, const float* __restrict__ W4b,
    const float* __restrict__ Wd2)
{
    const int L1n = 80016, L2n = 804, L3n = 1004, L4n = 4819, LDn = 143907;
    const int total = L1n + L2n + L3n + L4n + LDn;
    int stride = gridDim.x * blockDim.x;
    for (int i = blockIdx.x * blockDim.x + threadIdx.x; i < total; i += stride) {
        const char* p;
        int j = i;
        if (j < L1n)                 p = (const char*)W1b + (size_t)j * 128;
        else if ((j -= L1n) < L2n)   p = (const char*)W2b + (size_t)j * 128;
        else if ((j -= L2n) < L3n)   p = (const char*)W3b + (size_t)j * 128;
        else if ((j -= L3n) < L4n)   p = (const char*)W4b + (size_t)j * 128;
        else { j -= L4n;             p = (const char*)Wd2 + (size_t)j * 128; }
        asm volatile("prefetch.global.L2 [%0];" :: "l"(p));
    }
}

// ---------------- layer 1: partial GEMV, 1344 blocks x 256 thr ---------------
__global__ void __launch_bounds__(256) k_l1_partial(const float* __restrict__ x,
                                                    const float* __restrict__ W) {
    __shared__ float xs[RPC1];
    int bx = blockIdx.x, tid = threadIdx.x;
    int i0 = bx * RPC1;
    if (tid < RPC1) xs[tid] = x[i0 + tid];
    __syncthreads();
    if (tid < 250) {
        const float4* W4 = (const float4*)W;   // 1000 floats/row = 250 float4
        float4 a = make_float4(0.f, 0.f, 0.f, 0.f);
        #pragma unroll
        for (int r = 0; r < RPC1; ++r) {
            float4 w = __ldcs(&W4[(size_t)(i0 + r) * 250 + tid]);
            float xv = xs[r];
            a.x = fmaf(xv, w.x, a.x);
            a.y = fmaf(xv, w.y, a.y);
            a.z = fmaf(xv, w.z, a.z);
            a.w = fmaf(xv, w.w, a.w);
        }
        ((float4*)g_part1)[bx * 250 + tid] = a;
    }
}

// -------- mid: fold layer-1 partials -> h1 (shared), then layer-2 partials ---
// 40 blocks x 512 threads; block bx owns h1 rows [bx*25, bx*25+25)
__global__ void __launch_bounds__(512) k_mid(const float* __restrict__ bd1,
                                             const float* __restrict__ Wd2) {
    __shared__ float red[400];
    __shared__ float hs[RPC2];
    int tid = threadIdx.x, bx = blockIdx.x;
    int i0 = bx * RPC2;

    if (tid < 400) {                           // 25 rows x 16 chunk-groups
        int jj = tid % 25, g = tid / 25;
        float v = 0.f;
        int c0 = g * 84;                       // 1344/16
        #pragma unroll 12
        for (int c = 0; c < 84; ++c)
            v += g_part1[(c0 + c) * H1 + i0 + jj];
        red[tid] = v;
    }
    __syncthreads();
    if (tid < RPC2) {
        float s = bd1[i0 + tid];
        #pragma unroll
        for (int g = 0; g < 16; ++g) s += red[g * 25 + tid];
        hs[tid] = fmaxf(s, 0.f);
    }
    __syncthreads();
    if (tid < NS) {
        float acc = 0.f;
        const float* base = Wd2 + (size_t)i0 * 4605 + 15 * tid + 1;
        #pragma unroll
        for (int r = 0; r < RPC2; ++r)
            acc = fmaf(hs[r], base[(size_t)r * 4605], acc);
        g_part2[bx * 320 + tid] = acc;
    }
}

// ---------------- shared helpers ---------------------------------------------
__device__ __forceinline__ void fold_scalars(float* s_sh, const float* __restrict__ bd2,
                                             int sbase, int JB) {
    int tid = threadIdx.x;
    if (tid < JB) {
        int ks = sbase + tid;
        float v = bd2[15 * ks + 1];
        #pragma unroll
        for (int c = 0; c < KC2; ++c) v += g_part2[c * 320 + ks];
        s_sh[tid] = fmaxf(v, 0.f);
    }
}

// ---- seg1: 16 x 500 x 5121. warp-split-k, smem reduce, direct final write ---
// smem partition: s[0:16], h[16:16+8064] (504 rows x 16), red[8080:8080+4096]
__device__ __forceinline__ void seg1_body(
    float* smem, float* __restrict__ out, const float* __restrict__ bd2,
    const float* __restrict__ Wa, const float* __restrict__ ba,
    const float* __restrict__ Wb, const float* __restrict__ bb, int blk)
{
    const int O = 5121;
    float* s_sh = smem;
    float* h_sh = smem + 16;
    float* red  = smem + 8080;
    int tid = threadIdx.x;

    fold_scalars(s_sh, bd2, 0, 16);
    __syncthreads();

    // hidden: h[k][j] for k in [0,504), zero-padded beyond 500
    #pragma unroll
    for (int k = tid; k < 504; k += 256) {
        float av = 0.f, bv = 0.f;
        if (k < 500) { av = Wa[k]; bv = ba[k]; }
        float* hk = &h_sh[k * 16];
        #pragma unroll
        for (int j = 0; j < 16; ++j) {
            float v = (k < 500) ? fmaxf(fmaf(s_sh[j], av, bv), 0.f) : 0.f;
            hk[j] = v;
        }
    }
    __syncthreads();

    int w = tid >> 5, lane = tid & 31;
    int n = blk * 32 + lane;
    bool nok = (n < O);
    int k0 = w * 63;

    float acc[16];
    #pragma unroll
    for (int j = 0; j < 16; ++j) acc[j] = 0.f;

    #pragma unroll 21
    for (int r = 0; r < 63; ++r) {
        int k = k0 + r;
        float wv = (nok && k < 500) ? Wb[(size_t)k * O + n] : 0.f;
        const float* hr = &h_sh[k * 16];
        #pragma unroll
        for (int j = 0; j < 16; ++j)
            acc[j] = fmaf(hr[j], wv, acc[j]);
    }

    // reduce 8 warps in shared: red[w][j][lane]
    #pragma unroll
    for (int j = 0; j < 16; ++j)
        red[w * 512 + j * 32 + lane] = acc[j];
    __syncthreads();

    #pragma unroll
    for (int p = tid; p < 512; p += 256) {
        int j = p >> 5, ln = p & 31;
        int nn = blk * 32 + ln;
        if (nn < O) {
            float v = bb[nn];
            #pragma unroll
            for (int ww = 0; ww < 8; ++ww) v += red[ww * 512 + p];
            out[(size_t)j * O + nn] = fmaxf(v, 0.f);
        }
    }
}

// ---- direct segment: JB scalars x (256*CPT) cols, full K=100, final write ---
template<int JB, int CPT>
__device__ __forceinline__ void seg_direct(
    float* smem, float* __restrict__ out, const float* __restrict__ bd2,
    const float* __restrict__ Wa, const float* __restrict__ ba,
    const float* __restrict__ Wb, const float* __restrict__ bb,
    int O, int sbase, int jg0, int ct)
{
    float* s_sh = smem;
    float* h_sh = smem + 16;                   // [k][JB], 100*JB <= 400
    int tid = threadIdx.x;

    fold_scalars(s_sh, bd2, sbase + jg0, JB);
    __syncthreads();

    if (tid < 100) {
        float av = Wa[tid], bv = ba[tid];
        float* hk = &h_sh[tid * JB];
        #pragma unroll
        for (int j = 0; j < JB; ++j)
            hk[j] = fmaxf(fmaf(s_sh[j], av, bv), 0.f);
    }
    __syncthreads();

    int nb = ct * (256 * CPT) + tid;
    float acc[JB * CPT];
    #pragma unroll
    for (int i = 0; i < JB * CPT; ++i) acc[i] = 0.f;

    #pragma unroll 20
    for (int r = 0; r < 100; ++r) {
        const float* wrow = Wb + (size_t)r * O;
        float w[CPT];
        #pragma unroll
        for (int c = 0; c < CPT; ++c) {
            int n = nb + c * 256;
            w[c] = (n < O) ? wrow[n] : 0.f;
        }
        const float* hr = &h_sh[r * JB];
        #pragma unroll
        for (int j = 0; j < JB; ++j) {
            float hv = hr[j];
            #pragma unroll
            for (int c = 0; c < CPT; ++c)
                acc[j * CPT + c] = fmaf(hv, w[c], acc[j * CPT + c]);
        }
    }

    #pragma unroll
    for (int j = 0; j < JB; ++j) {
        #pragma unroll
        for (int c = 0; c < CPT; ++c) {
            int n = nb + c * 256;
            if (n < O)
                out[(size_t)(jg0 + j) * O + n] = fmaxf(acc[j * CPT + c] + bb[n], 0.f);
        }
    }
}

// seg1: 161 blocks (5121/32)   | seg3: 64 blocks (256 j / 4)
// seg2: 8 blocks (32 j / 4)    | seg4: 7 blocks (1542 cols / 256)
__global__ void __launch_bounds__(256) k_segments(
    float* __restrict__ out,
    const float* __restrict__ bd2,
    const float* __restrict__ W1a, const float* __restrict__ b1a, const float* __restrict__ W1b, const float* __restrict__ b1b,
    const float* __restrict__ W2a, const float* __restrict__ b2a, const float* __restrict__ W2b, const float* __restrict__ b2b,
    const float* __restrict__ W3a, const float* __restrict__ b3a, const float* __restrict__ W3b, const float* __restrict__ b3b,
    const float* __restrict__ W4a, const float* __restrict__ b4a, const float* __restrict__ W4b, const float* __restrict__ b4b)
{
    __shared__ float smem[12192];
    int b = blockIdx.x;
    if (b < 161) {
        seg1_body(smem, out, bd2, W1a, b1a, W1b, b1b, b);
    } else if (b < 225) {
        int jb = b - 161;
        seg_direct<4, 2>(smem, out + 90160, bd2, W3a, b3a, W3b, b3b, 321, 48, jb * 4, 0);
    } else if (b < 233) {
        int jb = b - 225;
        seg_direct<4, 2>(smem, out + 81936, bd2, W2a, b2a, W2b, b2b, 257, 16, jb * 4, 0);
    } else {
        int ct = b - 233;
        seg_direct<3, 1>(smem, out + 172336, bd2, W4a, b4a, W4b, b4b, 1542, 304, 0, ct);
    }
}

extern "C" void kernel_launch(void* const* d_in, const int* in_sizes, int n_in,
                              void* d_out, int out_size) {
    const float* x   = (const float*)d_in[0];
    const float* Wd1 = (const float*)d_in[1];
    const float* bd1 = (const float*)d_in[2];
    const float* Wd2 = (const float*)d_in[3];
    const float* bd2 = (const float*)d_in[4];
    const float* W1a = (const float*)d_in[5];
    const float* b1a = (const float*)d_in[6];
    const float* W1b = (const float*)d_in[7];
    const float* b1b = (const float*)d_in[8];
    const float* W2a = (const float*)d_in[9];
    const float* b2a = (const float*)d_in[10];
    const float* W2b = (const float*)d_in[11];
    const float* b2b = (const float*)d_in[12];
    const float* W3a = (const float*)d_in[13];
    const float* b3a = (const float*)d_in[14];
    const float* W3b = (const float*)d_in[15];
    const float* b3b = (const float*)d_in[16];
    const float* W4a = (const float*)d_in[17];
    const float* b4a = (const float*)d_in[18];
    const float* W4b = (const float*)d_in[19];
    const float* b4b = (const float*)d_in[20];
    float* out = (float*)d_out;

    // one-time host resources (created on first call, before graph capture)
    static cudaStream_t s1 = [](){ cudaStream_t s;
        cudaStreamCreateWithFlags(&s, cudaStreamNonBlocking); return s; }();
    static cudaEvent_t e0 = [](){ cudaEvent_t e;
        cudaEventCreateWithFlags(&e, cudaEventDisableTiming); return e; }();
    static cudaEvent_t e1 = [](){ cudaEvent_t e;
        cudaEventCreateWithFlags(&e, cudaEventDisableTiming); return e; }();

    // fork: prefetch Wb/Wd2 into L2 concurrently with the Wd1-streaming GEMV
    cudaEventRecord(e0, 0);
    cudaStreamWaitEvent(s1, e0, 0);
    k_prefetch<<<256, 256, 0, s1>>>(W1b, W2b, W3b, W4b, Wd2);
    cudaEventRecord(e1, s1);

    k_l1_partial<<<NCH1, 256>>>(x, Wd1);
    k_mid<<<KC2, 512>>>(bd1, Wd2);

    // join forked stream before the final kernel (required to close the capture)
    cudaStreamWaitEvent(0, e1, 0);
    k_segments<<<240, 256>>>(out, bd2,
                             W1a, b1a, W1b, b1b,
                             W2a, b2a, W2b, b2b,
                             W3a, b3a, W3b, b3b,
                             W4a, b4a, W4b, b4b);
}

// round 13
// speedup vs baseline: 1.0795x; 1.0795x over previous
#include <cuda_runtime.h>

#define H1   1000
#define NCH1 1344     // layer-1 row chunks
#define RPC1 25       // rows per chunk (1344*25 = 33600)

#define NS   307      // needed layer-2 columns (x2[15k+1])
#define KC2  40       // layer-2 k chunks
#define RPC2 25       // rows per chunk (40*25 = 1000)

// ---------------- scratch (__device__ globals; no allocations) ----------------
__device__ float g_part1[NCH1 * H1];         // layer-1 partial sums [chunk][j]
__device__ float g_part2[KC2 * 320];         // layer-2 partials for the 307 scalars

// ---------------- layer 1: partial GEMV, 1344 blocks x 256 thr ---------------
__global__ void __launch_bounds__(256) k_l1_partial(const float* __restrict__ x,
                                                    const float* __restrict__ W) {
    __shared__ float xs[RPC1];
    int bx = blockIdx.x, tid = threadIdx.x;
    int i0 = bx * RPC1;
    if (tid < RPC1) xs[tid] = x[i0 + tid];
    __syncthreads();
    if (tid < 250) {
        const float4* W4 = (const float4*)W;   // 1000 floats/row = 250 float4
        float4 a = make_float4(0.f, 0.f, 0.f, 0.f);
        #pragma unroll
        for (int r = 0; r < RPC1; ++r) {
            float4 w = __ldcs(&W4[(size_t)(i0 + r) * 250 + tid]);
            float xv = xs[r];
            a.x = fmaf(xv, w.x, a.x);
            a.y = fmaf(xv, w.y, a.y);
            a.z = fmaf(xv, w.z, a.z);
            a.w = fmaf(xv, w.w, a.w);
        }
        ((float4*)g_part1)[bx * 250 + tid] = a;
    }
}

// -------- mid: fold layer-1 partials -> h1 (shared), then layer-2 partials ---
// 40 blocks x 512 threads; block bx owns h1 rows [bx*25, bx*25+25)
__global__ void __launch_bounds__(512) k_mid(const float* __restrict__ bd1,
                                             const float* __restrict__ Wd2) {
    __shared__ float red[400];
    __shared__ float hs[RPC2];
    int tid = threadIdx.x, bx = blockIdx.x;
    int i0 = bx * RPC2;

    if (tid < 400) {                           // 25 rows x 16 chunk-groups
        int jj = tid % 25, g = tid / 25;
        float v = 0.f;
        int c0 = g * 84;                       // 1344/16
        #pragma unroll 12
        for (int c = 0; c < 84; ++c)
            v += g_part1[(c0 + c) * H1 + i0 + jj];
        red[tid] = v;
    }
    __syncthreads();
    if (tid < RPC2) {
        float s = bd1[i0 + tid];
        #pragma unroll
        for (int g = 0; g < 16; ++g) s += red[g * 25 + tid];
        hs[tid] = fmaxf(s, 0.f);
    }
    __syncthreads();
    if (tid < NS) {
        float acc = 0.f;
        const float* base = Wd2 + (size_t)i0 * 4605 + 15 * tid + 1;
        #pragma unroll
        for (int r = 0; r < RPC2; ++r)
            acc = fmaf(hs[r], base[(size_t)r * 4605], acc);
        g_part2[bx * 320 + tid] = acc;
    }
}

// ---------------- shared helpers ---------------------------------------------
__device__ __forceinline__ void fold_scalars(float* s_sh, const float* __restrict__ bd2,
                                             int sbase, int JB) {
    int tid = threadIdx.x;
    if (tid < JB) {
        int ks = sbase + tid;
        float v = bd2[15 * ks + 1];
        #pragma unroll
        for (int c = 0; c < KC2; ++c) v += g_part2[c * 320 + ks];
        s_sh[tid] = fmaxf(v, 0.f);
    }
}

// ---- seg1: 16 x 500 x 5121. warp-split-k, smem reduce, direct final write ---
// smem partition: s[0:16], h[16:16+8064] (504 rows x 16), red[8080:8080+4096]
// Inner k-loop uses explicit 9-deep LDG batching (63 = 7 x 9) to force MLP.
__device__ __forceinline__ void seg1_body(
    float* smem, float* __restrict__ out, const float* __restrict__ bd2,
    const float* __restrict__ Wa, const float* __restrict__ ba,
    const float* __restrict__ Wb, const float* __restrict__ bb, int blk)
{
    const int O = 5121;
    float* s_sh = smem;
    float* h_sh = smem + 16;
    float* red  = smem + 8080;
    int tid = threadIdx.x;

    fold_scalars(s_sh, bd2, 0, 16);
    __syncthreads();

    // hidden: h[k][j] for k in [0,504), zero-padded beyond 500
    #pragma unroll
    for (int k = tid; k < 504; k += 256) {
        float av = 0.f, bv = 0.f;
        if (k < 500) { av = Wa[k]; bv = ba[k]; }
        float* hk = &h_sh[k * 16];
        #pragma unroll
        for (int j = 0; j < 16; ++j) {
            float v = (k < 500) ? fmaxf(fmaf(s_sh[j], av, bv), 0.f) : 0.f;
            hk[j] = v;
        }
    }
    __syncthreads();

    int w = tid >> 5, lane = tid & 31;
    int n = blk * 32 + lane;
    bool nok = (n < O);
    int k0 = w * 63;

    float acc[16];
    #pragma unroll
    for (int j = 0; j < 16; ++j) acc[j] = 0.f;

    #pragma unroll
    for (int b = 0; b < 7; ++b) {
        int kb = k0 + b * 9;
        float wv[9];
        #pragma unroll
        for (int r = 0; r < 9; ++r) {
            int k = kb + r;
            wv[r] = (nok && k < 500) ? Wb[(size_t)k * O + n] : 0.f;
        }
        #pragma unroll
        for (int r = 0; r < 9; ++r) {
            const float* hr = &h_sh[(kb + r) * 16];
            #pragma unroll
            for (int j = 0; j < 16; ++j)
                acc[j] = fmaf(hr[j], wv[r], acc[j]);
        }
    }

    // reduce 8 warps in shared: red[w][j][lane]
    #pragma unroll
    for (int j = 0; j < 16; ++j)
        red[w * 512 + j * 32 + lane] = acc[j];
    __syncthreads();

    #pragma unroll
    for (int p = tid; p < 512; p += 256) {
        int j = p >> 5, ln = p & 31;
        int nn = blk * 32 + ln;
        if (nn < O) {
            float v = bb[nn];
            #pragma unroll
            for (int ww = 0; ww < 8; ++ww) v += red[ww * 512 + p];
            out[(size_t)j * O + nn] = fmaxf(v, 0.f);
        }
    }
}

// ---- direct segment: JB scalars x (256*CPT) cols, full K=100, final write ---
// K-loop uses explicit 10-deep LDG batching (100 = 10 x 10).
template<int JB, int CPT>
__device__ __forceinline__ void seg_direct(
    float* smem, float* __restrict__ out, const float* __restrict__ bd2,
    const float* __restrict__ Wa, const float* __restrict__ ba,
    const float* __restrict__ Wb, const float* __restrict__ bb,
    int O, int sbase, int jg0, int ct)
{
    float* s_sh = smem;
    float* h_sh = smem + 16;                   // [k][JB], 100*JB <= 400
    int tid = threadIdx.x;

    fold_scalars(s_sh, bd2, sbase + jg0, JB);
    __syncthreads();

    if (tid < 100) {
        float av = Wa[tid], bv = ba[tid];
        float* hk = &h_sh[tid * JB];
        #pragma unroll
        for (int j = 0; j < JB; ++j)
            hk[j] = fmaxf(fmaf(s_sh[j], av, bv), 0.f);
    }
    __syncthreads();

    int nb = ct * (256 * CPT) + tid;
    float acc[JB * CPT];
    #pragma unroll
    for (int i = 0; i < JB * CPT; ++i) acc[i] = 0.f;

    #pragma unroll
    for (int b = 0; b < 10; ++b) {
        float w[10 * CPT];
        #pragma unroll
        for (int r = 0; r < 10; ++r) {
            const float* wrow = Wb + (size_t)(b * 10 + r) * O;
            #pragma unroll
            for (int c = 0; c < CPT; ++c) {
                int nn = nb + c * 256;
                w[r * CPT + c] = (nn < O) ? wrow[nn] : 0.f;
            }
        }
        #pragma unroll
        for (int r = 0; r < 10; ++r) {
            const float* hr = &h_sh[(b * 10 + r) * JB];
            #pragma unroll
            for (int j = 0; j < JB; ++j) {
                float hv = hr[j];
                #pragma unroll
                for (int c = 0; c < CPT; ++c)
                    acc[j * CPT + c] = fmaf(hv, w[r * CPT + c], acc[j * CPT + c]);
            }
        }
    }

    #pragma unroll
    for (int j = 0; j < JB; ++j) {
        #pragma unroll
        for (int c = 0; c < CPT; ++c) {
            int n = nb + c * 256;
            if (n < O)
                out[(size_t)(jg0 + j) * O + n] = fmaxf(acc[j * CPT + c] + bb[n], 0.f);
        }
    }
}

// seg1: 161 blocks (5121/32)   | seg3: 64 blocks (256 j / 4)
// seg2: 8 blocks (32 j / 4)    | seg4: 7 blocks (1542 cols / 256)
__global__ void __launch_bounds__(256) k_segments(
    float* __restrict__ out,
    const float* __restrict__ bd2,
    const float* __restrict__ W1a, const float* __restrict__ b1a, const float* __restrict__ W1b, const float* __restrict__ b1b,
    const float* __restrict__ W2a, const float* __restrict__ b2a, const float* __restrict__ W2b, const float* __restrict__ b2b,
    const float* __restrict__ W3a, const float* __restrict__ b3a, const float* __restrict__ W3b, const float* __restrict__ b3b,
    const float* __restrict__ W4a, const float* __restrict__ b4a, const float* __restrict__ W4b, const float* __restrict__ b4b)
{
    __shared__ float smem[12192];
    int b = blockIdx.x;
    if (b < 161) {
        seg1_body(smem, out, bd2, W1a, b1a, W1b, b1b, b);
    } else if (b < 225) {
        int jb = b - 161;
        seg_direct<4, 2>(smem, out + 90160, bd2, W3a, b3a, W3b, b3b, 321, 48, jb * 4, 0);
    } else if (b < 233) {
        int jb = b - 225;
        seg_direct<4, 2>(smem, out + 81936, bd2, W2a, b2a, W2b, b2b, 257, 16, jb * 4, 0);
    } else {
        int ct = b - 233;
        seg_direct<3, 1>(smem, out + 172336, bd2, W4a, b4a, W4b, b4b, 1542, 304, 0, ct);
    }
}

extern "C" void kernel_launch(void* const* d_in, const int* in_sizes, int n_in,
                              void* d_out, int out_size) {
    const float* x   = (const float*)d_in[0];
    const float* Wd1 = (const float*)d_in[1];
    const float* bd1 = (const float*)d_in[2];
    const float* Wd2 = (const float*)d_in[3];
    const float* bd2 = (const float*)d_in[4];
    const float* W1a = (const float*)d_in[5];
    const float* b1a = (const float*)d_in[6];
    const float* W1b = (const float*)d_in[7];
    const float* b1b = (const float*)d_in[8];
    const float* W2a = (const float*)d_in[9];
    const float* b2a = (const float*)d_in[10];
    const float* W2b = (const float*)d_in[11];
    const float* b2b = (const float*)d_in[12];
    const float* W3a = (const float*)d_in[13];
    const float* b3a = (const float*)d_in[14];
    const float* W3b = (const float*)d_in[15];
    const float* b3b = (const float*)d_in[16];
    const float* W4a = (const float*)d_in[17];
    const float* b4a = (const float*)d_in[18];
    const float* W4b = (const float*)d_in[19];
    const float* b4b = (const float*)d_in[20];
    float* out = (float*)d_out;

    k_l1_partial<<<NCH1, 256>>>(x, Wd1);
    k_mid<<<KC2, 512>>>(bd1, Wd2);
    k_segments<<<240, 256>>>(out, bd2,
                             W1a, b1a, W1b, b1b,
                             W2a, b2a, W2b, b2b,
                             W3a, b3a, W3b, b3b,
                             W4a, b4a, W4b, b4b);
}